// round 15
// baseline (speedup 1.0000x reference)
#include <cuda_runtime.h>
#include <math.h>

typedef unsigned long long ull;

// ---------------- static scratch (no runtime allocation allowed) ----------------
#define MAXN 100000
#define MAXNODES 1000000

__device__ int   g_assoc[MAXNODES];
__device__ float g_Q   [(size_t)MAXN*100];
__device__ float g_K   [(size_t)MAXN*100];
__device__ float g_V   [(size_t)MAXN*100];
__device__ float g_AGG [(size_t)MAXN*100];   // skip projection (z @ Wskip^T + b)
__device__ float g_AGGW[(size_t)MAXN*100];   // unnormalized attention aggregation
__device__ float g_aden[(size_t)MAXN*2];     // softmax denominators per (node, head)

// ---------------- f32x2 packed-FMA helpers (full-rate FFMA on sm_103a) ----------
__device__ __forceinline__ float2 unpack2(ull v) {
    float2 r; asm("mov.b64 {%0,%1},%2;" : "=f"(r.x), "=f"(r.y) : "l"(v)); return r;
}
__device__ __forceinline__ void ffma2(ull& d, ull a, ull b) {
    asm("fma.rn.f32x2 %0,%1,%2,%3;" : "=l"(d) : "l"(a), "l"(b), "l"(d));
}
__device__ __forceinline__ float acc_sum(ull v) {
    float2 r = unpack2(v); return r.x + r.y;
}

// ---------------- init: AGGW = 0, aden = 0 ---------------------------------------
__global__ void init_kernel(int N) {
    int i = blockIdx.x * blockDim.x + threadIdx.x;
    if (i < N * 25) ((float4*)g_AGGW)[i] = make_float4(0.f, 0.f, 0.f, 0.f);
    if (i < 2 * N) g_aden[i] = 0.f;
}

__global__ void assoc_kernel(const int* __restrict__ n_id, int N) {
    int i = blockIdx.x * blockDim.x + threadIdx.x;
    if (i < N) g_assoc[n_id[i]] = i;
}

// =================================================================================
// Geometry: BM=192 (two 96-row sub-tiles), BN=100, TPB=320, TM=6 x TN=10.
// K-PAIRED f32x2 scheme (R8 xR11 synthesis): acc lanes = (even-k, odd-k) partials.
//   A row-major  a_s[r*SAE + k]   -> LDS.64 = natural (k,k+1) pair, no dup MOVs
//   B k-contig   b_s[c*SB  + k]   -> LDS.64 = natural pair; W/We are [out][k] so
//                                    the B fill is a straight padded copy.
// Final acc = lane0+lane1 (one FADD per output). 2 CTAs/SM = 20 warps, no spills.
// =================================================================================
#define TPB 320
#define SB  102      // b_s row stride (covers K<=101, +pad, even)
#define SAE 52       // a_s chunk stride (half-K, even)

// ---------------- fused Q/K/V/skip GEMM: C = z @ W^T + b -------------------------
__global__ void __launch_bounds__(TPB, 2) qkvs_kernel(
    const float* __restrict__ z,
    const float* __restrict__ W0, const float* __restrict__ b0,
    const float* __restrict__ W1, const float* __restrict__ b1,
    const float* __restrict__ W2, const float* __restrict__ b2v,
    const float* __restrict__ W3, const float* __restrict__ b3,
    int N, int ntiles)
{
    extern __shared__ float sm[];
    float* b_s    = sm;                  // [100][102] k-contiguous rows (W[out][k])
    float* a_s    = sm + 100 * SB;       // [192][52] row-major half-K chunk
    float* bias_s = a_s + 192 * SAE;     // [100]

    const float* W; const float* bias; float* out;
    switch (blockIdx.y) {
        case 0:  W = W0; bias = b0;  out = g_Q;   break;
        case 1:  W = W1; bias = b1;  out = g_K;   break;
        case 2:  W = W2; bias = b2v; out = g_V;   break;
        default: W = W3; bias = b3;  out = g_AGG; break;
    }
    int tid = threadIdx.x;

    for (int idx = tid; idx < 100 * SB; idx += TPB) {
        int o = idx / SB, k = idx - o * SB;
        b_s[idx] = (k < 100) ? W[o * 100 + k] : 0.f;
    }
    if (tid < 100) bias_s[tid] = bias[tid];

    int w = tid >> 5, lane = tid & 31;
    int th = (w >= 5) ? 1 : 0;           // sub-tile half
    int u  = (w - 5 * th) * 32 + lane;   // unit in [0,160)
    int rg = u / 10, cg = u % 10;
    int rbl = th * 96 + rg * 6;          // local row base in [0,192)
    int cb  = cg * 10;

    for (int tile = blockIdx.x; tile < ntiles; tile += gridDim.x) {
        int row0 = tile * 192;
        ull acc[6][10];
        #pragma unroll
        for (int i = 0; i < 6; i++)
            #pragma unroll
            for (int j = 0; j < 10; j++) acc[i][j] = 0ull;

        // K chunks: [0,52) and [52,100) -> 26 / 24 k-pairs
        #pragma unroll 1
        for (int c = 0; c < 2; c++) {
            int kb  = c * 52;
            int kn2 = c ? 24 : 26;           // float2 per row
            __syncthreads();
            // straight row-major copy: coalesced float2 LDG -> contiguous STS
            for (int idx = tid; idx < 192 * kn2; idx += TPB) {
                int r = idx / kn2, f = idx - r * kn2;
                int gr = row0 + r;
                float2 v = make_float2(0.f, 0.f);
                if (gr < N) v = *(const float2*)(z + (size_t)gr * 100 + kb + 2 * f);
                *(float2*)(a_s + r * SAE + 2 * f) = v;
            }
            __syncthreads();

            #pragma unroll 2
            for (int p = 0; p < kn2; p++) {
                int k = 2 * p;
                ull av[6];
                #pragma unroll
                for (int i = 0; i < 6; i++)
                    av[i] = *(const ull*)(a_s + (rbl + i) * SAE + k);
                const float* bp = b_s + kb + k;
                ull bj[5];
                #pragma unroll
                for (int j = 0; j < 5; j++) bj[j] = *(const ull*)(bp + (cb + j) * SB);
                #pragma unroll
                for (int i = 0; i < 6; i++)
                    #pragma unroll
                    for (int j = 0; j < 5; j++) ffma2(acc[i][j], av[i], bj[j]);
                #pragma unroll
                for (int j = 0; j < 5; j++) bj[j] = *(const ull*)(bp + (cb + 5 + j) * SB);
                #pragma unroll
                for (int i = 0; i < 6; i++)
                    #pragma unroll
                    for (int j = 0; j < 5; j++) ffma2(acc[i][5 + j], av[i], bj[j]);
            }
        }

        #pragma unroll
        for (int i = 0; i < 6; i++) {
            int gr = row0 + rbl + i;
            if (gr < N) {
                float2* op = (float2*)(out + (size_t)gr * 100 + cb);
                #pragma unroll
                for (int t = 0; t < 5; t++) {
                    float2 r;
                    r.x = acc_sum(acc[i][2 * t])     + bias_s[cb + 2 * t];
                    r.y = acc_sum(acc[i][2 * t + 1]) + bias_s[cb + 2 * t + 1];
                    op[t] = r;
                }
            }
        }
    }
}

// =================================================================================
// fused edge kernel: e_proj GEMM (attr generated in smem via __cosf) + alpha +
// max-free softmax weight + weighted scatter. K=102 padded (100 cos + msg + 0).
// =================================================================================
__global__ void __launch_bounds__(TPB, 2) edge_kernel(
    const float* __restrict__ lu, const float* __restrict__ t,
    const float* __restrict__ msg,
    const float* __restrict__ tw, const float* __restrict__ tb,
    const float* __restrict__ We, const int* __restrict__ ei,
    int E, int ntiles)
{
    extern __shared__ float sm[];
    float* b_s   = sm;                      // [100][102] k-contig (We[out][k], pad 0)
    float* a_s   = b_s + 100 * SB;          // [192][52] row-major attr chunk
    float* tw_s  = a_s + 192 * SAE;         // [100]
    float* tb_s  = tw_s + 100;              // [100]
    float* rel_s = tb_s + 100;              // [192]
    float* msg_s = rel_s + 192;             // [192]
    float* apart = msg_s + 192;             // [384] alpha partials, then w
    int*   sidx  = (int*)(apart + 384);     // [192]
    int*   didx  = sidx + 192;              // [192]

    int tid = threadIdx.x;
    for (int idx = tid; idx < 100 * SB; idx += TPB) {
        int o = idx / SB, k = idx - o * SB;
        b_s[idx] = (k < 101) ? We[o * 101 + k] : 0.f;
    }
    if (tid < 100) { tw_s[tid] = tw[tid]; tb_s[tid] = tb[tid]; }

    int w = tid >> 5, lane = tid & 31;
    int th = (w >= 5) ? 1 : 0;
    int u  = (w - 5 * th) * 32 + lane;
    int rg = u / 10, cg = u % 10;
    int rbl = th * 96 + rg * 6;
    int cb  = cg * 10;
    int h   = (cg >= 5) ? 1 : 0;             // head of this colgroup (TN=10 never spans)
    const float inv = 0.14142135623730951f;  // 1/sqrt(50)

    for (int tile = blockIdx.x; tile < ntiles; tile += gridDim.x) {
        int e0 = tile * 192;
        __syncthreads();                     // prev tile fully consumed
        if (tid < 192) {
            int e = e0 + tid; float rv = 0.f, mv = 0.f; int s = 0, d = 0;
            if (e < E) { s = ei[e]; d = ei[E + e]; rv = lu[s] - t[e]; mv = msg[e]; }
            rel_s[tid] = rv; msg_s[tid] = mv; sidx[tid] = s; didx[tid] = d;
        }
        for (int idx = tid; idx < 384; idx += TPB) apart[idx] = 0.f;

        ull acc[6][10];
        #pragma unroll
        for (int i = 0; i < 6; i++)
            #pragma unroll
            for (int j = 0; j < 10; j++) acc[i][j] = 0ull;

        // K chunks: [0,52) cos only; [52,102): cos(52..99), msg(100), zero(101)
        #pragma unroll 1
        for (int c = 0; c < 2; c++) {
            int kb = c * 52;
            int kn = c ? 50 : 52;
            __syncthreads();                 // meta ready (c0) / prev mainloop done
            for (int idx = tid; idx < 192 * kn; idx += TPB) {
                int r = idx / kn, kk = idx - r * kn;
                int gk = kb + kk;
                float v;
                if (gk < 100)       v = __cosf(fmaf(rel_s[r], tw_s[gk], tb_s[gk]));
                else if (gk == 100) v = msg_s[r];
                else                v = 0.f;
                a_s[r * SAE + kk] = v;
            }
            __syncthreads();

            int pn = (kn + 1) >> 1;          // 26 / 25 k-pairs
            #pragma unroll 2
            for (int p = 0; p < pn; p++) {
                int k = 2 * p;
                ull av[6];
                #pragma unroll
                for (int i = 0; i < 6; i++)
                    av[i] = *(const ull*)(a_s + (rbl + i) * SAE + k);
                const float* bp = b_s + kb + k;
                ull bj[5];
                #pragma unroll
                for (int j = 0; j < 5; j++) bj[j] = *(const ull*)(bp + (cb + j) * SB);
                #pragma unroll
                for (int i = 0; i < 6; i++)
                    #pragma unroll
                    for (int j = 0; j < 5; j++) ffma2(acc[i][j], av[i], bj[j]);
                #pragma unroll
                for (int j = 0; j < 5; j++) bj[j] = *(const ull*)(bp + (cb + 5 + j) * SB);
                #pragma unroll
                for (int i = 0; i < 6; i++)
                    #pragma unroll
                    for (int j = 0; j < 5; j++) ffma2(acc[i][5 + j], av[i], bj[j]);
            }
        }

        // ---- alpha partials: q[dst] . (k[src] + e_proj) over this colgroup ----
        #pragma unroll
        for (int i = 0; i < 6; i++) {
            int r = rbl + i, e = e0 + r;
            if (e < E) {
                int s = sidx[r], d = didx[r];
                const float2* qp = (const float2*)(g_Q + (size_t)d * 100 + cb);
                const float2* kp = (const float2*)(g_K + (size_t)s * 100 + cb);
                float part = 0.f;
                #pragma unroll
                for (int t2 = 0; t2 < 5; t2++) {
                    float2 qv = qp[t2];
                    float2 kv = kp[t2];
                    part = fmaf(qv.x, kv.x + acc_sum(acc[i][2 * t2]),     part);
                    part = fmaf(qv.y, kv.y + acc_sum(acc[i][2 * t2 + 1]), part);
                }
                atomicAdd(&apart[2 * r + h], part);
            }
        }
        __syncthreads();

        // ---- w = exp(alpha) (max-free), accumulate denominators ----
        for (int idx = tid; idx < 384; idx += TPB) {
            int r = idx >> 1, hh = idx & 1;
            int e = e0 + r;
            if (e < E) {
                float ww = __expf(apart[idx] * inv);
                apart[idx] = ww;                        // reuse as w_s
                atomicAdd(&g_aden[2 * didx[r] + hh], ww);
            }
        }
        __syncthreads();

        // ---- scatter: AGGW[dst] += (v[src] + e_proj) * w  (vector REDs) ----
        #pragma unroll
        for (int i = 0; i < 6; i++) {
            int r = rbl + i, e = e0 + r;
            if (e < E) {
                int s = sidx[r], d = didx[r];
                const float2* vp = (const float2*)(g_V + (size_t)s * 100 + cb);
                float ww = apart[2 * r + h];
                float m[10];
                #pragma unroll
                for (int t2 = 0; t2 < 5; t2++) {
                    float2 vv = vp[t2];
                    m[2 * t2]     = (vv.x + acc_sum(acc[i][2 * t2]))     * ww;
                    m[2 * t2 + 1] = (vv.y + acc_sum(acc[i][2 * t2 + 1])) * ww;
                }
                float* op = g_AGGW + (size_t)d * 100 + cb;
                if ((cg & 1) == 0) {   // cb % 4 == 0 : 4+4+2
                    atomicAdd((float4*)op,       make_float4(m[0], m[1], m[2], m[3]));
                    atomicAdd((float4*)(op + 4), make_float4(m[4], m[5], m[6], m[7]));
                    atomicAdd((float2*)(op + 8), make_float2(m[8], m[9]));
                } else {               // cb % 4 == 2 : 2+4+4
                    atomicAdd((float2*)op,       make_float2(m[0], m[1]));
                    atomicAdd((float4*)(op + 2), make_float4(m[2], m[3], m[4], m[5]));
                    atomicAdd((float4*)(op + 6), make_float4(m[6], m[7], m[8], m[9]));
                }
            }
        }
    }
}

// =================================================================================
// link predictor with fused normalization:
// z_out = AGG(skip) + AGGW/aden ; out = relu(z_s@Ws^T + z_d@Wd^T + b) @ Wf^T + bf
// =================================================================================
__global__ void __launch_bounds__(128) linkpred_kernel(
    const float* __restrict__ Wsrc, const float* __restrict__ bsrc,
    const float* __restrict__ Wdst, const float* __restrict__ bdst,
    const float* __restrict__ Wf,   const float* __restrict__ bf,
    const int* __restrict__ src, const int* __restrict__ dst,
    float* __restrict__ out, int B)
{
    extern __shared__ float sm[];
    float* Ws   = sm;                 // [100][101] padded
    float* Wd   = Ws + 100 * 101;
    float* bsum = Wd + 100 * 101;
    float* wf   = bsum + 100;
    float* zrow = wf + 100;           // 4 warps * 200

    int tid = threadIdx.x, lane = tid & 31, warp = tid >> 5;
    for (int idx = tid; idx < 10000; idx += 128) {
        int o = idx / 100, k = idx - o * 100;
        Ws[o * 101 + k] = Wsrc[idx];
        Wd[o * 101 + k] = Wdst[idx];
    }
    if (tid < 100) { bsum[tid] = bsrc[tid] + bdst[tid]; wf[tid] = Wf[tid]; }
    __syncthreads();

    float bf0 = bf[0];
    float* zs = zrow + warp * 200;
    float* zd = zs + 100;

    for (int p = blockIdx.x * 4 + warp; p < B; p += gridDim.x * 4) {
        int sp = g_assoc[src[p]];
        int dp = g_assoc[dst[p]];
        float ds0 = g_aden[2 * sp], ds1 = g_aden[2 * sp + 1];
        float dd0 = g_aden[2 * dp], dd1 = g_aden[2 * dp + 1];
        float is0 = ds0 > 0.f ? 1.f / ds0 : 0.f;
        float is1 = ds1 > 0.f ? 1.f / ds1 : 0.f;
        float id0 = dd0 > 0.f ? 1.f / dd0 : 0.f;
        float id1 = dd1 > 0.f ? 1.f / dd1 : 0.f;
        for (int c = lane; c < 100; c += 32) {
            float invs = (c < 50) ? is0 : is1;
            float invd = (c < 50) ? id0 : id1;
            zs[c] = fmaf(g_AGGW[(size_t)sp * 100 + c], invs, g_AGG[(size_t)sp * 100 + c]);
            zd[c] = fmaf(g_AGGW[(size_t)dp * 100 + c], invd, g_AGG[(size_t)dp * 100 + c]);
        }
        __syncwarp();
        float acc = 0.f;
        for (int o = lane; o < 100; o += 32) {
            float hh = bsum[o];
            const float* wsr = Ws + o * 101;
            const float* wdr = Wd + o * 101;
            #pragma unroll 10
            for (int k = 0; k < 100; k++) {
                hh = fmaf(wsr[k], zs[k], hh);
                hh = fmaf(wdr[k], zd[k], hh);
            }
            hh = fmaxf(hh, 0.f);
            acc = fmaf(hh, wf[o], acc);
        }
        #pragma unroll
        for (int o = 16; o; o >>= 1) acc += __shfl_xor_sync(0xffffffffu, acc, o);
        if (lane == 0) out[p] = acc + bf0;
        __syncwarp();
    }
}

// ---------------- launch ----------------------------------------------------------
extern "C" void kernel_launch(void* const* d_in, const int* in_sizes, int n_in,
                              void* d_out, int out_size)
{
    const float* z     = (const float*)d_in[0];
    const float* lu    = (const float*)d_in[1];
    const float* t     = (const float*)d_in[2];
    const float* msg   = (const float*)d_in[3];
    const float* tw    = (const float*)d_in[4];
    const float* tb    = (const float*)d_in[5];
    const float* Wq    = (const float*)d_in[6];
    const float* bq    = (const float*)d_in[7];
    const float* Wk    = (const float*)d_in[8];
    const float* bk    = (const float*)d_in[9];
    const float* Wv    = (const float*)d_in[10];
    const float* bv    = (const float*)d_in[11];
    const float* We    = (const float*)d_in[12];
    const float* Wskip = (const float*)d_in[13];
    const float* bskip = (const float*)d_in[14];
    const float* Wsrc  = (const float*)d_in[15];
    const float* bsrc  = (const float*)d_in[16];
    const float* Wdst  = (const float*)d_in[17];
    const float* bdst  = (const float*)d_in[18];
    const float* Wf    = (const float*)d_in[19];
    const float* bf    = (const float*)d_in[20];
    const int*   n_id  = (const int*)d_in[21];
    const int*   srcp  = (const int*)d_in[22];
    const int*   dstp  = (const int*)d_in[23];
    const int*   ei    = (const int*)d_in[24];

    int N = in_sizes[0] / 100;
    int E = in_sizes[2];
    int B = in_sizes[22];
    float* out = (float*)d_out;

    int ntilesN = (N + 191) / 192;
    int ntilesE = (E + 191) / 192;

    const int SMEM_QKVS = (100 * SB + 192 * SAE + 100) * 4;                    // ~80.2 KB
    const int SMEM_EDGE = (100 * SB + 192 * SAE + 100 + 100 + 192 + 192 + 384
                           + 192 + 192) * 4;                                   // ~85.4 KB
    const int SMEM_LP   = (2 * 100 * 101 + 200 + 4 * 200) * 4;                 // ~84.8 KB

    cudaFuncSetAttribute(qkvs_kernel,     cudaFuncAttributeMaxDynamicSharedMemorySize, SMEM_QKVS);
    cudaFuncSetAttribute(edge_kernel,     cudaFuncAttributeMaxDynamicSharedMemorySize, SMEM_EDGE);
    cudaFuncSetAttribute(linkpred_kernel, cudaFuncAttributeMaxDynamicSharedMemorySize, SMEM_LP);

    init_kernel<<<(N * 25 + 255) / 256, 256>>>(N);
    assoc_kernel<<<(N + 255) / 256, 256>>>(n_id, N);

    dim3 gq(74, 4);    // 296 persistent CTAs (148 SMs x 2), 4 weight sets
    qkvs_kernel<<<gq, TPB, SMEM_QKVS>>>(z, Wq, bq, Wk, bk, Wv, bv, Wskip, bskip,
                                        N, ntilesN);

    edge_kernel<<<296, TPB, SMEM_EDGE>>>(lu, t, msg, tw, tb, We, ei, E, ntilesE);

    linkpred_kernel<<<296, 128, SMEM_LP>>>(Wsrc, bsrc, Wdst, bdst, Wf, bf,
                                           srcp, dstp, out, B);
}